// round 15
// baseline (speedup 1.0000x reference)
#include <cuda_runtime.h>
#include <cuda_bf16.h>
#include <math.h>
#include <stdint.h>

// Problem constants
#define NB   16
#define NN   8192
#define DHH  64
#define DCAT 128
#define BD   (NB * DCAT)   // 2048
#define HALF_W (NB * DHH)  // 1024

// Feature layout: (N, 2048) bf16 row-major; inp half at n*2048 + b*64 + d, st half at +1024.

// -------- scratch (device globals) --------
__device__ float g_PRE[(size_t)NN * NB * (DCAT + DHH)];   // [0,128): ru preact ; then c preact
__device__ __nv_bfloat16 g_Sb  [(size_t)2 * NN * NN];
__device__ __nv_bfloat16 g_Xb  [(size_t)NN * BD];
__device__ __nv_bfloat16 g_T1ab[(size_t)NN * BD];
__device__ __nv_bfloat16 g_T1cb[(size_t)NN * BD];
__device__ __nv_bfloat16 g_T2ab[(size_t)NN * BD];
__device__ __nv_bfloat16 g_T2cb[(size_t)NN * BD];
__device__ __nv_bfloat16 g_Wrub[640 * 128];
__device__ __nv_bfloat16 g_Wcb [640 * 64];

// ---------------- helpers ----------------
__device__ __forceinline__ void cp_async16(uint32_t dst, const void* src) {
    asm volatile("cp.async.cg.shared.global [%0], [%1], 16;\n"
                 : : "r"(dst), "l"(src) : "memory");
}
__device__ __forceinline__ void cp_async16_pred(uint32_t dst, const void* src, bool pred) {
    const uint32_t sz = pred ? 16u : 0u;
    asm volatile("cp.async.cg.shared.global [%0], [%1], 16, %2;\n"
                 : : "r"(dst), "l"(src), "r"(sz) : "memory");
}
__device__ __forceinline__ void cp_commit() {
    asm volatile("cp.async.commit_group;\n" : : : "memory");
}
template <int N>
__device__ __forceinline__ void cp_wait() {
    asm volatile("cp.async.wait_group %0;\n" : : "n"(N) : "memory");
}
__device__ __forceinline__ void ldsm_x4(uint32_t& r0, uint32_t& r1, uint32_t& r2, uint32_t& r3,
                                        uint32_t addr) {
    asm volatile("ldmatrix.sync.aligned.m8n8.x4.shared.b16 {%0,%1,%2,%3}, [%4];\n"
                 : "=r"(r0), "=r"(r1), "=r"(r2), "=r"(r3) : "r"(addr));
}
__device__ __forceinline__ void ldsm_x4_t(uint32_t& r0, uint32_t& r1, uint32_t& r2, uint32_t& r3,
                                          uint32_t addr) {
    asm volatile("ldmatrix.sync.aligned.m8n8.x4.trans.shared.b16 {%0,%1,%2,%3}, [%4];\n"
                 : "=r"(r0), "=r"(r1), "=r"(r2), "=r"(r3) : "r"(addr));
}
__device__ __forceinline__ void mma_bf16(float* c, const uint32_t* a, uint32_t b0, uint32_t b1) {
    asm volatile("mma.sync.aligned.m16n8k16.row.col.f32.bf16.bf16.f32 "
                 "{%0,%1,%2,%3}, {%4,%5,%6,%7}, {%8,%9}, {%0,%1,%2,%3};\n"
                 : "+f"(c[0]), "+f"(c[1]), "+f"(c[2]), "+f"(c[3])
                 : "r"(a[0]), "r"(a[1]), "r"(a[2]), "r"(a[3]), "r"(b0), "r"(b1));
}
__device__ __forceinline__ float sigmoidf_(float x) {
    return 1.f / (1.f + expf(-x));
}

// ===================== bf16 GEMM, 128x128x32, 5-stage, z-batched, bf16 I/O =====================
#define HASTR 40
#define HBSTR 136
#define NSTG  5
#define ASZH  (128 * HASTR)
#define BSZH  (32 * HBSTR)
#define HG_SMEM ((ASZH + BSZH) * 2 * NSTG)   // 94720 bytes

__global__ __launch_bounds__(256, 2)
void hgemm_kernel(const __nv_bfloat16* __restrict__ A0, const __nv_bfloat16* __restrict__ A1, int lda,
                  const __nv_bfloat16* __restrict__ B0, const __nv_bfloat16* __restrict__ B1, int ldb,
                  __nv_bfloat16* __restrict__ C0, __nv_bfloat16* __restrict__ C1, int ldc,
                  const __nv_bfloat16* __restrict__ D0, const __nv_bfloat16* __restrict__ D1, int ldd,
                  float alpha, float beta, int K)
{
    extern __shared__ __align__(16) char smem_raw[];
    __nv_bfloat16* Asm = (__nv_bfloat16*)smem_raw;
    __nv_bfloat16* Bsm = Asm + NSTG * ASZH;

    const int z = blockIdx.z;
    const __nv_bfloat16* __restrict__ A = z ? A1 : A0;
    const __nv_bfloat16* __restrict__ B = z ? B1 : B0;
    __nv_bfloat16* __restrict__ C = z ? C1 : C0;
    const __nv_bfloat16* __restrict__ D = z ? D1 : D0;

    const int tid = threadIdx.x;
    const int bm = blockIdx.y * 128;
    const int bn = blockIdx.x * 128;

    const int arow = tid >> 1;
    const int acolh = (tid & 1) * 16;
    const int browk = tid >> 3;
    const int bcolh = (tid & 7) * 16;

    const __nv_bfloat16* Ag = A + (size_t)(bm + arow) * lda + acolh;
    const __nv_bfloat16* Bg = B + (size_t)browk * ldb + bn + bcolh;

    const uint32_t sa = (uint32_t)__cvta_generic_to_shared(Asm);
    const uint32_t sb = (uint32_t)__cvta_generic_to_shared(Bsm);
    const uint32_t sa_off = (arow * HASTR + acolh) * 2;
    const uint32_t sb_off = (browk * HBSTR + bcolh) * 2;

    const int lane = tid & 31;
    const int w    = tid >> 5;
    const int wm   = (w & 1) * 64;
    const int wn   = (w >> 1) * 32;
    const int gid  = lane >> 2;
    const int tig  = lane & 3;

    const int a_row_l  = wm + (lane & 15);
    const int a_colh_l = (lane >> 4) << 3;
    const int b_rowk_l = lane & 15;
    const int b_colh_l = wn + ((lane >> 4) << 3);

    float acc[4][4][4];
#pragma unroll
    for (int mm = 0; mm < 4; mm++)
#pragma unroll
        for (int nn = 0; nn < 4; nn++)
#pragma unroll
            for (int r = 0; r < 4; r++) acc[mm][nn][r] = 0.f;

    const int ntiles = K >> 5;

#pragma unroll
    for (int s = 0; s < NSTG - 1; ++s) {
        if (s < ntiles) {
            const int kt = s * 32;
            uint32_t da = sa + s * (ASZH * 2) + sa_off;
            cp_async16(da,      Ag + kt);
            cp_async16(da + 16, Ag + kt + 8);
            uint32_t db = sb + s * (BSZH * 2) + sb_off;
            cp_async16(db,      Bg + (size_t)kt * ldb);
            cp_async16(db + 16, Bg + (size_t)kt * ldb + 8);
        }
        cp_commit();
    }

    int buf = 0;        // = i % NSTG
    int nstage = NSTG - 1;  // stage index for tile i+NSTG-1 (= (i+NSTG-1) % NSTG)
    for (int i = 0; i < ntiles; ++i) {
        cp_wait<NSTG - 2>();
        __syncthreads();

        const uint32_t sa_b = sa + buf * (ASZH * 2);
        const uint32_t sb_b = sb + buf * (BSZH * 2);

#pragma unroll
        for (int ks = 0; ks < 2; ks++) {
            uint32_t a[4][4];
            uint32_t b[2][4];
#pragma unroll
            for (int mmi = 0; mmi < 4; mmi++) {
                const uint32_t addr = sa_b +
                    ((a_row_l + mmi * 16) * HASTR + ks * 16 + a_colh_l) * 2;
                ldsm_x4(a[mmi][0], a[mmi][1], a[mmi][2], a[mmi][3], addr);
            }
#pragma unroll
            for (int p = 0; p < 2; p++) {
                const uint32_t addr = sb_b +
                    ((ks * 16 + b_rowk_l) * HBSTR + b_colh_l + p * 16) * 2;
                ldsm_x4_t(b[p][0], b[p][1], b[p][2], b[p][3], addr);
            }
#pragma unroll
            for (int mmi = 0; mmi < 4; mmi++)
#pragma unroll
                for (int nni = 0; nni < 4; nni++) {
                    const uint32_t b0 = b[nni >> 1][(nni & 1) * 2];
                    const uint32_t b1 = b[nni >> 1][(nni & 1) * 2 + 1];
                    mma_bf16(acc[mmi][nni], a[mmi], b0, b1);
                }
        }

        const int nt = i + NSTG - 1;
        if (nt < ntiles) {
            // nstage == nt % NSTG by induction
            const int kt = nt * 32;
            uint32_t da = sa + nstage * (ASZH * 2) + sa_off;
            cp_async16(da,      Ag + kt);
            cp_async16(da + 16, Ag + kt + 8);
            uint32_t db = sb + nstage * (BSZH * 2) + sb_off;
            cp_async16(db,      Bg + (size_t)kt * ldb);
            cp_async16(db + 16, Bg + (size_t)kt * ldb + 8);
        }
        cp_commit();

        buf = (buf + 1 == NSTG) ? 0 : buf + 1;
        nstage = (nstage + 1 == NSTG) ? 0 : nstage + 1;
    }

    // epilogue: bf16 out, optional bf16 D combine
#pragma unroll
    for (int mmi = 0; mmi < 4; mmi++) {
        const int row = bm + wm + mmi * 16 + gid;
#pragma unroll
        for (int nni = 0; nni < 4; nni++) {
            const int col = bn + wn + nni * 8 + tig * 2;
            float2 v0, v1;
            v0.x = alpha * acc[mmi][nni][0];
            v0.y = alpha * acc[mmi][nni][1];
            v1.x = alpha * acc[mmi][nni][2];
            v1.y = alpha * acc[mmi][nni][3];
            if (beta != 0.f) {
                const __nv_bfloat162 d0 = *(const __nv_bfloat162*)&D[(size_t)row * ldd + col];
                const __nv_bfloat162 d1 = *(const __nv_bfloat162*)&D[(size_t)(row + 8) * ldd + col];
                v0.x += beta * __bfloat162float(d0.x);
                v0.y += beta * __bfloat162float(d0.y);
                v1.x += beta * __bfloat162float(d1.x);
                v1.y += beta * __bfloat162float(d1.y);
            }
            *(__nv_bfloat162*)&C[(size_t)row * ldc + col]       = __floats2bfloat162_rn(v0.x, v0.y);
            *(__nv_bfloat162*)&C[(size_t)(row + 8) * ldc + col] = __floats2bfloat162_rn(v1.x, v1.y);
        }
    }
}

// ============ bf16 fused projection: [X,T1,T2,T1',T2'] (K=640, bf16) @ Wb + bias -> fp32 ============
#define PASTR 40
#define PBSTR 136

__global__ __launch_bounds__(256, 2)
void bf16_proj5_kernel(const __nv_bfloat16* __restrict__ A0, const __nv_bfloat16* __restrict__ A1,
                       const __nv_bfloat16* __restrict__ A2, const __nv_bfloat16* __restrict__ A3,
                       const __nv_bfloat16* __restrict__ A4,
                       const __nv_bfloat16* __restrict__ W, int Nc,
                       float* __restrict__ C,
                       const float* __restrict__ bias)
{
    __shared__ __align__(16) __nv_bfloat16 As[2][128 * PASTR];
    __shared__ __align__(16) __nv_bfloat16 Bs[2][32 * PBSTR];

    const int tid = threadIdx.x;
    const int bm = blockIdx.y * 128;

    const int ar = tid >> 1;
    const int aseg = (tid & 1) * 16;
    const int m = bm + ar;
    const size_t rowbase = ((size_t)(m >> 4)) * 2048 + (size_t)(m & 15) * 64;
    const int br = tid >> 3;
    const int bc = (tid & 7) * 16;
    const bool bp0 = bc < Nc;
    const bool bp1 = (bc + 8) < Nc;

    const uint32_t sa = (uint32_t)__cvta_generic_to_shared(&As[0][0]);
    const uint32_t sb = (uint32_t)__cvta_generic_to_shared(&Bs[0][0]);
    const uint32_t sa_off = (ar * PASTR + aseg) * 2;
    const uint32_t sb_off = (br * PBSTR + bc) * 2;

    const int lane = tid & 31;
    const int w    = tid >> 5;
    const int wm   = (w & 1) * 64;
    const int wn   = (w >> 1) * 32;
    const int gid  = lane >> 2;
    const int tig  = lane & 3;

    const int a_row_l  = wm + (lane & 15);
    const int a_colh_l = (lane >> 4) << 3;
    const int b_rowk_l = lane & 15;
    const int b_colh_l = wn + ((lane >> 4) << 3);

    float acc[4][4][4];
#pragma unroll
    for (int mm = 0; mm < 4; mm++)
#pragma unroll
        for (int nn = 0; nn < 4; nn++)
#pragma unroll
            for (int r = 0; r < 4; r++) acc[mm][nn][r] = 0.f;

    auto a_src = [&](int kt) -> const __nv_bfloat16* {
        const int kk = kt + aseg;
        const int bufi = kk >> 7;
        const int k = kk & 127;
        const __nv_bfloat16* Ab = A0;
        if (bufi == 1) Ab = A1;
        else if (bufi == 2) Ab = A2;
        else if (bufi == 3) Ab = A3;
        else if (bufi == 4) Ab = A4;
        return Ab + rowbase + (k < 64 ? k : 1024 + k - 64);
    };

    {
        const __nv_bfloat16* srcA = a_src(0);
        uint32_t da = sa + sa_off;
        cp_async16(da,      srcA);
        cp_async16(da + 16, srcA + 8);
        uint32_t db = sb + sb_off;
        cp_async16_pred(db,      W + (size_t)br * Nc + bc,     bp0);
        cp_async16_pred(db + 16, W + (size_t)br * Nc + bc + 8, bp1);
        cp_commit();
    }

    int buf = 0;
    for (int kt = 0; kt < 640; kt += 32) {
        const bool has_next = (kt + 32) < 640;
        if (has_next) {
            const int nb_ = buf ^ 1;
            const int kt2 = kt + 32;
            const __nv_bfloat16* srcA = a_src(kt2);
            uint32_t da = sa + nb_ * (128 * PASTR * 2) + sa_off;
            cp_async16(da,      srcA);
            cp_async16(da + 16, srcA + 8);
            uint32_t db = sb + nb_ * (32 * PBSTR * 2) + sb_off;
            cp_async16_pred(db,      W + (size_t)(kt2 + br) * Nc + bc,     bp0);
            cp_async16_pred(db + 16, W + (size_t)(kt2 + br) * Nc + bc + 8, bp1);
            cp_commit();
            cp_wait<1>();
        } else {
            cp_wait<0>();
        }
        __syncthreads();

        const uint32_t sa_b = sa + buf * (128 * PASTR * 2);
        const uint32_t sb_b = sb + buf * (32 * PBSTR * 2);

#pragma unroll
        for (int ks = 0; ks < 2; ks++) {
            uint32_t a[4][4];
            uint32_t b[2][4];
#pragma unroll
            for (int mmi = 0; mmi < 4; mmi++) {
                const uint32_t addr = sa_b +
                    ((a_row_l + mmi * 16) * PASTR + ks * 16 + a_colh_l) * 2;
                ldsm_x4(a[mmi][0], a[mmi][1], a[mmi][2], a[mmi][3], addr);
            }
#pragma unroll
            for (int p = 0; p < 2; p++) {
                const uint32_t addr = sb_b +
                    ((ks * 16 + b_rowk_l) * PBSTR + b_colh_l + p * 16) * 2;
                ldsm_x4_t(b[p][0], b[p][1], b[p][2], b[p][3], addr);
            }
#pragma unroll
            for (int mmi = 0; mmi < 4; mmi++)
#pragma unroll
                for (int nni = 0; nni < 4; nni++) {
                    const uint32_t b0 = b[nni >> 1][(nni & 1) * 2];
                    const uint32_t b1 = b[nni >> 1][(nni & 1) * 2 + 1];
                    mma_bf16(acc[mmi][nni], a[mmi], b0, b1);
                }
        }
        __syncthreads();
        buf ^= 1;
    }

#pragma unroll
    for (int mmi = 0; mmi < 4; mmi++) {
        const int row = bm + wm + mmi * 16 + gid;
#pragma unroll
        for (int nni = 0; nni < 4; nni++) {
            const int col = wn + nni * 8 + tig * 2;
            if (col < Nc) {
                float2 v0, v1;
                v0.x = acc[mmi][nni][0];
                v0.y = acc[mmi][nni][1];
                v1.x = acc[mmi][nni][2];
                v1.y = acc[mmi][nni][3];
                if (bias) {
                    const float2 bv = *(const float2*)&bias[col];
                    v0.x += bv.x; v0.y += bv.y;
                    v1.x += bv.x; v1.y += bv.y;
                }
                *(float2*)&C[(size_t)row * Nc + col]       = v0;
                *(float2*)&C[(size_t)(row + 8) * Nc + col] = v1;
            }
        }
    }
}

// ============================ fused prep ============================
#define PREP_GS  131072
#define PREP_GX  32768
#define PREP_GW1 80
#define PREP_GW2 40
#define PREP_TOTAL (PREP_GS + PREP_GX + PREP_GW1 + PREP_GW2)

__device__ __forceinline__ void cast4(const float4* __restrict__ src, uint2* __restrict__ dst,
                                      size_t i, size_t n4)
{
    if (i >= n4) return;
    const float4 v = src[i];
    const __nv_bfloat162 lo = __floats2bfloat162_rn(v.x, v.y);
    const __nv_bfloat162 hi = __floats2bfloat162_rn(v.z, v.w);
    uint2 o;
    o.x = *reinterpret_cast<const uint32_t*>(&lo);
    o.y = *reinterpret_cast<const uint32_t*>(&hi);
    dst[i] = o;
}

__global__ void prep_kernel(const float* __restrict__ inputs,
                            const float* __restrict__ states,
                            const float* __restrict__ supports,
                            const float* __restrict__ W_ru,
                            const float* __restrict__ W_c,
                            __nv_bfloat16* __restrict__ Xb,
                            __nv_bfloat16* __restrict__ Sb,
                            __nv_bfloat16* __restrict__ Wrub,
                            __nv_bfloat16* __restrict__ Wcb)
{
    const int blk = blockIdx.x;
    if (blk < PREP_GS) {
        const size_t i = (size_t)blk * 256 + threadIdx.x;
        cast4((const float4*)supports, (uint2*)Sb, i, (size_t)2 * NN * NN / 4);
    } else if (blk < PREP_GS + PREP_GX) {
        const int i = (blk - PREP_GS) * 256 + threadIdx.x;
        if (i < NN * BD / 2) {
            const int n = i >> 10;
            const int r = (i & 1023) * 2;
            float2 v;
            if (r < HALF_W) {
                const int b = r >> 6, d = r & 63;
                v = *(const float2*)&inputs[((size_t)b * NN + n) * DHH + d];
            } else {
                const int r2 = r - HALF_W;
                const int b = r2 >> 6, d = r2 & 63;
                v = *(const float2*)&states[((size_t)b * NN + n) * DHH + d];
            }
            *(__nv_bfloat162*)&Xb[(size_t)n * BD + r] = __floats2bfloat162_rn(v.x, v.y);
        }
    } else if (blk < PREP_GS + PREP_GX + PREP_GW1) {
        const size_t i = (size_t)(blk - PREP_GS - PREP_GX) * 256 + threadIdx.x;
        cast4((const float4*)W_ru, (uint2*)Wrub, i, 640 * 128 / 4);
    } else {
        const size_t i = (size_t)(blk - PREP_GS - PREP_GX - PREP_GW1) * 256 + threadIdx.x;
        cast4((const float4*)W_c, (uint2*)Wcb, i, 640 * 64 / 4);
    }
}

// ============================ elementwise ============================

__global__ void gate_kernel(const float* __restrict__ states,
                            const float* __restrict__ PRE,
                            __nv_bfloat16* __restrict__ Xb)
{
    int i = blockIdx.x * blockDim.x + threadIdx.x;          // over NN*NB*32
    if (i >= NN * NB * 32) return;
    const int n = i / (NB * 32);
    const int r0 = i - n * (NB * 32);
    const int b = r0 >> 5;
    const int d = (r0 & 31) * 2;
    const size_t prow = (size_t)(n * NB + b) * DCAT;
    const float2 pr = *(const float2*)&PRE[prow + d];
    const float r0f = sigmoidf_(pr.x);
    const float r1f = sigmoidf_(pr.y);
    const float2 st = *(const float2*)&states[((size_t)b * NN + n) * DHH + d];
    *(__nv_bfloat162*)&Xb[(size_t)n * BD + HALF_W + (size_t)b * DHH + d] =
        __floats2bfloat162_rn(r0f * st.x, r1f * st.y);
}

__global__ void final_kernel(const float* __restrict__ states,
                             const float* __restrict__ PRE,    // ru preact (row stride 128)
                             const float* __restrict__ PREC,   // c preact (row stride 64)
                             float* __restrict__ out,
                             int dup)
{
    int i = blockIdx.x * blockDim.x + threadIdx.x;          // over NN*NB*32 (2 elems/thread)
    if (i >= NN * NB * 32) return;
    const int n = i / (NB * 32);
    const int r0 = i - n * (NB * 32);
    const int b = r0 >> 5;
    const int d = (r0 & 31) * 2;
    const size_t row = (size_t)n * NB + b;
    const float2 pu = *(const float2*)&PRE[row * DCAT + DHH + d];
    const float2 pc = *(const float2*)&PREC[row * DHH + d];
    const float u0 = sigmoidf_(pu.x);
    const float u1 = sigmoidf_(pu.y);
    const float c0 = tanhf(pc.x);
    const float c1 = tanhf(pc.y);
    const float2 st = *(const float2*)&states[((size_t)b * NN + n) * DHH + d];
    float2 ns;
    ns.x = u0 * st.x + (1.f - u0) * c0;
    ns.y = u1 * st.y + (1.f - u1) * c1;
    const size_t o = ((size_t)b * NN + n) * DHH + d;
    *(float2*)&out[o] = ns;
    if (dup) {
        const size_t total = (size_t)NB * NN * DHH;
        *(float2*)&out[total + o] = ns;
    }
}

// ============================ launch ============================

extern "C" void kernel_launch(void* const* d_in, const int* in_sizes, int n_in,
                              void* d_out, int out_size)
{
    const float* inputs   = (const float*)d_in[0];
    const float* states   = (const float*)d_in[1];
    const float* supports = (const float*)d_in[2];
    const float* W_ru     = (const float*)d_in[3];
    const float* b_ru     = (const float*)d_in[4];
    const float* W_c      = (const float*)d_in[5];
    const float* b_c      = (const float*)d_in[6];
    float* out = (float*)d_out;

    float *pPRE;
    __nv_bfloat16 *pSb, *pXb, *pT1ab, *pT1cb, *pT2ab, *pT2cb, *pWrub, *pWcb;
    cudaGetSymbolAddress((void**)&pPRE,  g_PRE);
    cudaGetSymbolAddress((void**)&pSb,   g_Sb);
    cudaGetSymbolAddress((void**)&pXb,   g_Xb);
    cudaGetSymbolAddress((void**)&pT1ab, g_T1ab);
    cudaGetSymbolAddress((void**)&pT1cb, g_T1cb);
    cudaGetSymbolAddress((void**)&pT2ab, g_T2ab);
    cudaGetSymbolAddress((void**)&pT2cb, g_T2cb);
    cudaGetSymbolAddress((void**)&pWrub, g_Wrub);
    cudaGetSymbolAddress((void**)&pWcb,  g_Wcb);

    float* pPREC = pPRE + (size_t)NN * NB * DCAT;

    cudaFuncSetAttribute(hgemm_kernel,
                         cudaFuncAttributeMaxDynamicSharedMemorySize, HG_SMEM);

    const __nv_bfloat16* S0b = pSb;
    const __nv_bfloat16* S1b = pSb + (size_t)NN * NN;

    const dim3 blk(256);
    const dim3 gFull2(BD / 128, NN / 128, 2);        // 2048 CTAs
    const dim3 gHalf2(HALF_W / 128, NN / 128, 2);    // 1024 CTAs
    const dim3 gProj(1, (NN * NB) / 128);            // (1, 1024)

    const size_t total = (size_t)NB * NN * DHH;
    const int dup = ((size_t)out_size >= 2 * total) ? 1 : 0;

    // ---- fused prep (S cast + build_x + W casts) ----
    prep_kernel<<<PREP_TOTAL, blk>>>(inputs, states, supports, W_ru, W_c,
                                     pXb, pSb, pWrub, pWcb);

    // ---------- phase 1 hops (full width), both supports batched ----------
    hgemm_kernel<<<gFull2, blk, HG_SMEM>>>(S0b, S1b, NN, pXb, pXb, BD,
                                           pT1ab, pT1cb, BD,
                                           (const __nv_bfloat16*)0, (const __nv_bfloat16*)0, 0,
                                           1.f, 0.f, NN);
    hgemm_kernel<<<gFull2, blk, HG_SMEM>>>(S0b, S1b, NN, pT1ab, pT1cb, BD,
                                           pT2ab, pT2cb, BD,
                                           pXb, pXb, BD,
                                           2.f, -1.f, NN);

    // ---------- fused ru projection (K=640, bf16) ----------
    bf16_proj5_kernel<<<gProj, blk>>>(pXb, pT1ab, pT2ab, pT1cb, pT2cb,
                                      pWrub, 2 * DHH, pPRE, b_ru);

    // ---------- gates (r only; u consumed later straight from PRE) ----------
    gate_kernel<<<(NN * NB * 32 + 255) / 256, blk>>>(states, pPRE, pXb);

    // ---------- phase 2 hops (st halves only, width 1024), batched ----------
    hgemm_kernel<<<gHalf2, blk, HG_SMEM>>>(S0b, S1b, NN,
                                           pXb + HALF_W, pXb + HALF_W, BD,
                                           pT1ab + HALF_W, pT1cb + HALF_W, BD,
                                           (const __nv_bfloat16*)0, (const __nv_bfloat16*)0, 0,
                                           1.f, 0.f, NN);
    hgemm_kernel<<<gHalf2, blk, HG_SMEM>>>(S0b, S1b, NN,
                                           pT1ab + HALF_W, pT1cb + HALF_W, BD,
                                           pT2ab + HALF_W, pT2cb + HALF_W, BD,
                                           pXb + HALF_W, pXb + HALF_W, BD,
                                           2.f, -1.f, NN);

    // ---------- fused c projection (K=640, Nc=64, bf16) -> disjoint PREC ----------
    bf16_proj5_kernel<<<gProj, blk>>>(pXb, pT1ab, pT2ab, pT1cb, pT2cb,
                                      pWcb, DHH, pPREC, b_c);

    // ---------- final state (u recomputed from ru-PRE) ----------
    final_kernel<<<(NN * NB * 32 + 255) / 256, blk>>>(states, pPRE, pPREC, out, dup);
}

// round 16
// speedup vs baseline: 1.0300x; 1.0300x over previous
#include <cuda_runtime.h>
#include <cuda_bf16.h>
#include <math.h>
#include <stdint.h>

// Problem constants
#define NB   16
#define NN   8192
#define DHH  64
#define DCAT 128
#define BD   (NB * DCAT)   // 2048
#define HALF_W (NB * DHH)  // 1024

// Feature layout: (N, 2048) bf16 row-major; inp half at n*2048 + b*64 + d, st half at +1024.

// -------- scratch (device globals) --------
__device__ float g_PRE[(size_t)NN * NB * (DCAT + DHH)];   // [0,128): ru preact ; then c preact
__device__ __nv_bfloat16 g_Sb  [(size_t)2 * NN * NN];
__device__ __nv_bfloat16 g_Xb  [(size_t)NN * BD];
__device__ __nv_bfloat16 g_T1ab[(size_t)NN * BD];
__device__ __nv_bfloat16 g_T1cb[(size_t)NN * BD];
__device__ __nv_bfloat16 g_T2ab[(size_t)NN * BD];
__device__ __nv_bfloat16 g_T2cb[(size_t)NN * BD];
__device__ __nv_bfloat16 g_Wrub[640 * 128];
__device__ __nv_bfloat16 g_Wcb [640 * 64];

// ---------------- helpers ----------------
__device__ __forceinline__ void cp_async16(uint32_t dst, const void* src) {
    asm volatile("cp.async.cg.shared.global [%0], [%1], 16;\n"
                 : : "r"(dst), "l"(src) : "memory");
}
__device__ __forceinline__ void cp_async16_pred(uint32_t dst, const void* src, bool pred) {
    const uint32_t sz = pred ? 16u : 0u;
    asm volatile("cp.async.cg.shared.global [%0], [%1], 16, %2;\n"
                 : : "r"(dst), "l"(src), "r"(sz) : "memory");
}
__device__ __forceinline__ void cp_commit() {
    asm volatile("cp.async.commit_group;\n" : : : "memory");
}
template <int N>
__device__ __forceinline__ void cp_wait() {
    asm volatile("cp.async.wait_group %0;\n" : : "n"(N) : "memory");
}
__device__ __forceinline__ void ldsm_x4(uint32_t& r0, uint32_t& r1, uint32_t& r2, uint32_t& r3,
                                        uint32_t addr) {
    asm volatile("ldmatrix.sync.aligned.m8n8.x4.shared.b16 {%0,%1,%2,%3}, [%4];\n"
                 : "=r"(r0), "=r"(r1), "=r"(r2), "=r"(r3) : "r"(addr));
}
__device__ __forceinline__ void ldsm_x4_t(uint32_t& r0, uint32_t& r1, uint32_t& r2, uint32_t& r3,
                                          uint32_t addr) {
    asm volatile("ldmatrix.sync.aligned.m8n8.x4.trans.shared.b16 {%0,%1,%2,%3}, [%4];\n"
                 : "=r"(r0), "=r"(r1), "=r"(r2), "=r"(r3) : "r"(addr));
}
__device__ __forceinline__ void mma_bf16(float* c, const uint32_t* a, uint32_t b0, uint32_t b1) {
    asm volatile("mma.sync.aligned.m16n8k16.row.col.f32.bf16.bf16.f32 "
                 "{%0,%1,%2,%3}, {%4,%5,%6,%7}, {%8,%9}, {%0,%1,%2,%3};\n"
                 : "+f"(c[0]), "+f"(c[1]), "+f"(c[2]), "+f"(c[3])
                 : "r"(a[0]), "r"(a[1]), "r"(a[2]), "r"(a[3]), "r"(b0), "r"(b1));
}
__device__ __forceinline__ float sigmoidf_(float x) {
    return 1.f / (1.f + expf(-x));
}

// ===================== bf16 GEMM, 128x128x32, 4-stage, z-batched, bf16 I/O =====================
#define HASTR 40
#define HBSTR 136
#define NSTG  4
#define ASZH  (128 * HASTR)
#define BSZH  (32 * HBSTR)
#define HG_SMEM ((ASZH + BSZH) * 2 * NSTG)   // 75776 bytes

__global__ __launch_bounds__(256, 2)
void hgemm_kernel(const __nv_bfloat16* __restrict__ A0, const __nv_bfloat16* __restrict__ A1, int lda,
                  const __nv_bfloat16* __restrict__ B0, const __nv_bfloat16* __restrict__ B1, int ldb,
                  __nv_bfloat16* __restrict__ C0, __nv_bfloat16* __restrict__ C1, int ldc,
                  const __nv_bfloat16* __restrict__ D0, const __nv_bfloat16* __restrict__ D1, int ldd,
                  float alpha, float beta, int K)
{
    extern __shared__ __align__(16) char smem_raw[];
    __nv_bfloat16* Asm = (__nv_bfloat16*)smem_raw;
    __nv_bfloat16* Bsm = Asm + NSTG * ASZH;

    const int z = blockIdx.z;
    const __nv_bfloat16* __restrict__ A = z ? A1 : A0;
    const __nv_bfloat16* __restrict__ B = z ? B1 : B0;
    __nv_bfloat16* __restrict__ C = z ? C1 : C0;
    const __nv_bfloat16* __restrict__ D = z ? D1 : D0;

    const int tid = threadIdx.x;
    const int bm = blockIdx.y * 128;
    const int bn = blockIdx.x * 128;

    const int arow = tid >> 1;
    const int acolh = (tid & 1) * 16;
    const int browk = tid >> 3;
    const int bcolh = (tid & 7) * 16;

    const __nv_bfloat16* Ag = A + (size_t)(bm + arow) * lda + acolh;
    const __nv_bfloat16* Bg = B + (size_t)browk * ldb + bn + bcolh;

    const uint32_t sa = (uint32_t)__cvta_generic_to_shared(Asm);
    const uint32_t sb = (uint32_t)__cvta_generic_to_shared(Bsm);
    const uint32_t sa_off = (arow * HASTR + acolh) * 2;
    const uint32_t sb_off = (browk * HBSTR + bcolh) * 2;

    const int lane = tid & 31;
    const int w    = tid >> 5;
    const int wm   = (w & 1) * 64;
    const int wn   = (w >> 1) * 32;
    const int gid  = lane >> 2;
    const int tig  = lane & 3;

    const int a_row_l  = wm + (lane & 15);
    const int a_colh_l = (lane >> 4) << 3;
    const int b_rowk_l = lane & 15;
    const int b_colh_l = wn + ((lane >> 4) << 3);

    float acc[4][4][4];
#pragma unroll
    for (int mm = 0; mm < 4; mm++)
#pragma unroll
        for (int nn = 0; nn < 4; nn++)
#pragma unroll
            for (int r = 0; r < 4; r++) acc[mm][nn][r] = 0.f;

    const int ntiles = K >> 5;

#pragma unroll
    for (int s = 0; s < NSTG - 1; ++s) {
        if (s < ntiles) {
            const int kt = s * 32;
            uint32_t da = sa + s * (ASZH * 2) + sa_off;
            cp_async16(da,      Ag + kt);
            cp_async16(da + 16, Ag + kt + 8);
            uint32_t db = sb + s * (BSZH * 2) + sb_off;
            cp_async16(db,      Bg + (size_t)kt * ldb);
            cp_async16(db + 16, Bg + (size_t)kt * ldb + 8);
        }
        cp_commit();
    }

    for (int i = 0; i < ntiles; ++i) {
        cp_wait<NSTG - 2>();
        __syncthreads();

        const int buf = i & (NSTG - 1);
        const uint32_t sa_b = sa + buf * (ASZH * 2);
        const uint32_t sb_b = sb + buf * (BSZH * 2);

#pragma unroll
        for (int ks = 0; ks < 2; ks++) {
            uint32_t a[4][4];
            uint32_t b[2][4];
#pragma unroll
            for (int mmi = 0; mmi < 4; mmi++) {
                const uint32_t addr = sa_b +
                    ((a_row_l + mmi * 16) * HASTR + ks * 16 + a_colh_l) * 2;
                ldsm_x4(a[mmi][0], a[mmi][1], a[mmi][2], a[mmi][3], addr);
            }
#pragma unroll
            for (int p = 0; p < 2; p++) {
                const uint32_t addr = sb_b +
                    ((ks * 16 + b_rowk_l) * HBSTR + b_colh_l + p * 16) * 2;
                ldsm_x4_t(b[p][0], b[p][1], b[p][2], b[p][3], addr);
            }
#pragma unroll
            for (int mmi = 0; mmi < 4; mmi++)
#pragma unroll
                for (int nni = 0; nni < 4; nni++) {
                    const uint32_t b0 = b[nni >> 1][(nni & 1) * 2];
                    const uint32_t b1 = b[nni >> 1][(nni & 1) * 2 + 1];
                    mma_bf16(acc[mmi][nni], a[mmi], b0, b1);
                }
        }

        const int nt = i + NSTG - 1;
        if (nt < ntiles) {
            const int nb_ = nt & (NSTG - 1);
            const int kt = nt * 32;
            uint32_t da = sa + nb_ * (ASZH * 2) + sa_off;
            cp_async16(da,      Ag + kt);
            cp_async16(da + 16, Ag + kt + 8);
            uint32_t db = sb + nb_ * (BSZH * 2) + sb_off;
            cp_async16(db,      Bg + (size_t)kt * ldb);
            cp_async16(db + 16, Bg + (size_t)kt * ldb + 8);
        }
        cp_commit();
    }

    // epilogue: bf16 out, optional bf16 D combine
#pragma unroll
    for (int mmi = 0; mmi < 4; mmi++) {
        const int row = bm + wm + mmi * 16 + gid;
#pragma unroll
        for (int nni = 0; nni < 4; nni++) {
            const int col = bn + wn + nni * 8 + tig * 2;
            float2 v0, v1;
            v0.x = alpha * acc[mmi][nni][0];
            v0.y = alpha * acc[mmi][nni][1];
            v1.x = alpha * acc[mmi][nni][2];
            v1.y = alpha * acc[mmi][nni][3];
            if (beta != 0.f) {
                const __nv_bfloat162 d0 = *(const __nv_bfloat162*)&D[(size_t)row * ldd + col];
                const __nv_bfloat162 d1 = *(const __nv_bfloat162*)&D[(size_t)(row + 8) * ldd + col];
                v0.x += beta * __bfloat162float(d0.x);
                v0.y += beta * __bfloat162float(d0.y);
                v1.x += beta * __bfloat162float(d1.x);
                v1.y += beta * __bfloat162float(d1.y);
            }
            *(__nv_bfloat162*)&C[(size_t)row * ldc + col]       = __floats2bfloat162_rn(v0.x, v0.y);
            *(__nv_bfloat162*)&C[(size_t)(row + 8) * ldc + col] = __floats2bfloat162_rn(v1.x, v1.y);
        }
    }
}

// ============ bf16 fused projection: [X,T1,T2,T1',T2'] (K=640, bf16) @ Wb + bias -> fp32 ============
#define PASTR 40
#define PBSTR 136

__global__ __launch_bounds__(256, 2)
void bf16_proj5_kernel(const __nv_bfloat16* __restrict__ A0, const __nv_bfloat16* __restrict__ A1,
                       const __nv_bfloat16* __restrict__ A2, const __nv_bfloat16* __restrict__ A3,
                       const __nv_bfloat16* __restrict__ A4,
                       const __nv_bfloat16* __restrict__ W, int Nc,
                       float* __restrict__ C,
                       const float* __restrict__ bias)
{
    __shared__ __align__(16) __nv_bfloat16 As[2][128 * PASTR];
    __shared__ __align__(16) __nv_bfloat16 Bs[2][32 * PBSTR];

    const int tid = threadIdx.x;
    const int bm = blockIdx.y * 128;

    const int ar = tid >> 1;
    const int aseg = (tid & 1) * 16;
    const int m = bm + ar;
    const size_t rowbase = ((size_t)(m >> 4)) * 2048 + (size_t)(m & 15) * 64;
    const int br = tid >> 3;
    const int bc = (tid & 7) * 16;
    const bool bp0 = bc < Nc;
    const bool bp1 = (bc + 8) < Nc;

    const uint32_t sa = (uint32_t)__cvta_generic_to_shared(&As[0][0]);
    const uint32_t sb = (uint32_t)__cvta_generic_to_shared(&Bs[0][0]);
    const uint32_t sa_off = (ar * PASTR + aseg) * 2;
    const uint32_t sb_off = (br * PBSTR + bc) * 2;

    const int lane = tid & 31;
    const int w    = tid >> 5;
    const int wm   = (w & 1) * 64;
    const int wn   = (w >> 1) * 32;
    const int gid  = lane >> 2;
    const int tig  = lane & 3;

    const int a_row_l  = wm + (lane & 15);
    const int a_colh_l = (lane >> 4) << 3;
    const int b_rowk_l = lane & 15;
    const int b_colh_l = wn + ((lane >> 4) << 3);

    float acc[4][4][4];
#pragma unroll
    for (int mm = 0; mm < 4; mm++)
#pragma unroll
        for (int nn = 0; nn < 4; nn++)
#pragma unroll
            for (int r = 0; r < 4; r++) acc[mm][nn][r] = 0.f;

    auto a_src = [&](int kt) -> const __nv_bfloat16* {
        const int kk = kt + aseg;
        const int bufi = kk >> 7;
        const int k = kk & 127;
        const __nv_bfloat16* Ab = A0;
        if (bufi == 1) Ab = A1;
        else if (bufi == 2) Ab = A2;
        else if (bufi == 3) Ab = A3;
        else if (bufi == 4) Ab = A4;
        return Ab + rowbase + (k < 64 ? k : 1024 + k - 64);
    };

    {
        const __nv_bfloat16* srcA = a_src(0);
        uint32_t da = sa + sa_off;
        cp_async16(da,      srcA);
        cp_async16(da + 16, srcA + 8);
        uint32_t db = sb + sb_off;
        cp_async16_pred(db,      W + (size_t)br * Nc + bc,     bp0);
        cp_async16_pred(db + 16, W + (size_t)br * Nc + bc + 8, bp1);
        cp_commit();
    }

    int buf = 0;
    for (int kt = 0; kt < 640; kt += 32) {
        const bool has_next = (kt + 32) < 640;
        if (has_next) {
            const int nb_ = buf ^ 1;
            const int kt2 = kt + 32;
            const __nv_bfloat16* srcA = a_src(kt2);
            uint32_t da = sa + nb_ * (128 * PASTR * 2) + sa_off;
            cp_async16(da,      srcA);
            cp_async16(da + 16, srcA + 8);
            uint32_t db = sb + nb_ * (32 * PBSTR * 2) + sb_off;
            cp_async16_pred(db,      W + (size_t)(kt2 + br) * Nc + bc,     bp0);
            cp_async16_pred(db + 16, W + (size_t)(kt2 + br) * Nc + bc + 8, bp1);
            cp_commit();
            cp_wait<1>();
        } else {
            cp_wait<0>();
        }
        __syncthreads();

        const uint32_t sa_b = sa + buf * (128 * PASTR * 2);
        const uint32_t sb_b = sb + buf * (32 * PBSTR * 2);

#pragma unroll
        for (int ks = 0; ks < 2; ks++) {
            uint32_t a[4][4];
            uint32_t b[2][4];
#pragma unroll
            for (int mmi = 0; mmi < 4; mmi++) {
                const uint32_t addr = sa_b +
                    ((a_row_l + mmi * 16) * PASTR + ks * 16 + a_colh_l) * 2;
                ldsm_x4(a[mmi][0], a[mmi][1], a[mmi][2], a[mmi][3], addr);
            }
#pragma unroll
            for (int p = 0; p < 2; p++) {
                const uint32_t addr = sb_b +
                    ((ks * 16 + b_rowk_l) * PBSTR + b_colh_l + p * 16) * 2;
                ldsm_x4_t(b[p][0], b[p][1], b[p][2], b[p][3], addr);
            }
#pragma unroll
            for (int mmi = 0; mmi < 4; mmi++)
#pragma unroll
                for (int nni = 0; nni < 4; nni++) {
                    const uint32_t b0 = b[nni >> 1][(nni & 1) * 2];
                    const uint32_t b1 = b[nni >> 1][(nni & 1) * 2 + 1];
                    mma_bf16(acc[mmi][nni], a[mmi], b0, b1);
                }
        }
        __syncthreads();
        buf ^= 1;
    }

#pragma unroll
    for (int mmi = 0; mmi < 4; mmi++) {
        const int row = bm + wm + mmi * 16 + gid;
#pragma unroll
        for (int nni = 0; nni < 4; nni++) {
            const int col = wn + nni * 8 + tig * 2;
            if (col < Nc) {
                float2 v0, v1;
                v0.x = acc[mmi][nni][0];
                v0.y = acc[mmi][nni][1];
                v1.x = acc[mmi][nni][2];
                v1.y = acc[mmi][nni][3];
                if (bias) {
                    const float2 bv = *(const float2*)&bias[col];
                    v0.x += bv.x; v0.y += bv.y;
                    v1.x += bv.x; v1.y += bv.y;
                }
                *(float2*)&C[(size_t)row * Nc + col]       = v0;
                *(float2*)&C[(size_t)(row + 8) * Nc + col] = v1;
            }
        }
    }
}

// ============================ fused prep ============================
#define PREP_GS  131072
#define PREP_GX  32768
#define PREP_GW1 80
#define PREP_GW2 40
#define PREP_TOTAL (PREP_GS + PREP_GX + PREP_GW1 + PREP_GW2)

__device__ __forceinline__ void cast4(const float4* __restrict__ src, uint2* __restrict__ dst,
                                      size_t i, size_t n4)
{
    if (i >= n4) return;
    const float4 v = src[i];
    const __nv_bfloat162 lo = __floats2bfloat162_rn(v.x, v.y);
    const __nv_bfloat162 hi = __floats2bfloat162_rn(v.z, v.w);
    uint2 o;
    o.x = *reinterpret_cast<const uint32_t*>(&lo);
    o.y = *reinterpret_cast<const uint32_t*>(&hi);
    dst[i] = o;
}

__global__ void prep_kernel(const float* __restrict__ inputs,
                            const float* __restrict__ states,
                            const float* __restrict__ supports,
                            const float* __restrict__ W_ru,
                            const float* __restrict__ W_c,
                            __nv_bfloat16* __restrict__ Xb,
                            __nv_bfloat16* __restrict__ Sb,
                            __nv_bfloat16* __restrict__ Wrub,
                            __nv_bfloat16* __restrict__ Wcb)
{
    const int blk = blockIdx.x;
    if (blk < PREP_GS) {
        const size_t i = (size_t)blk * 256 + threadIdx.x;
        cast4((const float4*)supports, (uint2*)Sb, i, (size_t)2 * NN * NN / 4);
    } else if (blk < PREP_GS + PREP_GX) {
        const int i = (blk - PREP_GS) * 256 + threadIdx.x;
        if (i < NN * BD / 2) {
            const int n = i >> 10;
            const int r = (i & 1023) * 2;
            float2 v;
            if (r < HALF_W) {
                const int b = r >> 6, d = r & 63;
                v = *(const float2*)&inputs[((size_t)b * NN + n) * DHH + d];
            } else {
                const int r2 = r - HALF_W;
                const int b = r2 >> 6, d = r2 & 63;
                v = *(const float2*)&states[((size_t)b * NN + n) * DHH + d];
            }
            *(__nv_bfloat162*)&Xb[(size_t)n * BD + r] = __floats2bfloat162_rn(v.x, v.y);
        }
    } else if (blk < PREP_GS + PREP_GX + PREP_GW1) {
        const size_t i = (size_t)(blk - PREP_GS - PREP_GX) * 256 + threadIdx.x;
        cast4((const float4*)W_ru, (uint2*)Wrub, i, 640 * 128 / 4);
    } else {
        const size_t i = (size_t)(blk - PREP_GS - PREP_GX - PREP_GW1) * 256 + threadIdx.x;
        cast4((const float4*)W_c, (uint2*)Wcb, i, 640 * 64 / 4);
    }
}

// ============================ elementwise ============================

__global__ void gate_kernel(const float* __restrict__ states,
                            const float* __restrict__ PRE,
                            __nv_bfloat16* __restrict__ Xb)
{
    int i = blockIdx.x * blockDim.x + threadIdx.x;          // over NN*NB*32
    if (i >= NN * NB * 32) return;
    const int n = i / (NB * 32);
    const int r0 = i - n * (NB * 32);
    const int b = r0 >> 5;
    const int d = (r0 & 31) * 2;
    const size_t prow = (size_t)(n * NB + b) * DCAT;
    const float2 pr = *(const float2*)&PRE[prow + d];
    const float r0f = sigmoidf_(pr.x);
    const float r1f = sigmoidf_(pr.y);
    const float2 st = *(const float2*)&states[((size_t)b * NN + n) * DHH + d];
    *(__nv_bfloat162*)&Xb[(size_t)n * BD + HALF_W + (size_t)b * DHH + d] =
        __floats2bfloat162_rn(r0f * st.x, r1f * st.y);
}

__global__ void final_kernel(const float* __restrict__ states,
                             const float* __restrict__ PRE,    // ru preact (row stride 128)
                             const float* __restrict__ PREC,   // c preact (row stride 64)
                             float* __restrict__ out,
                             int dup)
{
    int i = blockIdx.x * blockDim.x + threadIdx.x;          // over NN*NB*32 (2 elems/thread)
    if (i >= NN * NB * 32) return;
    const int n = i / (NB * 32);
    const int r0 = i - n * (NB * 32);
    const int b = r0 >> 5;
    const int d = (r0 & 31) * 2;
    const size_t row = (size_t)n * NB + b;
    const float2 pu = *(const float2*)&PRE[row * DCAT + DHH + d];
    const float2 pc = *(const float2*)&PREC[row * DHH + d];
    const float u0 = sigmoidf_(pu.x);
    const float u1 = sigmoidf_(pu.y);
    const float c0 = tanhf(pc.x);
    const float c1 = tanhf(pc.y);
    const float2 st = *(const float2*)&states[((size_t)b * NN + n) * DHH + d];
    float2 ns;
    ns.x = u0 * st.x + (1.f - u0) * c0;
    ns.y = u1 * st.y + (1.f - u1) * c1;
    const size_t o = ((size_t)b * NN + n) * DHH + d;
    *(float2*)&out[o] = ns;
    if (dup) {
        const size_t total = (size_t)NB * NN * DHH;
        *(float2*)&out[total + o] = ns;
    }
}

// ============================ launch ============================

extern "C" void kernel_launch(void* const* d_in, const int* in_sizes, int n_in,
                              void* d_out, int out_size)
{
    const float* inputs   = (const float*)d_in[0];
    const float* states   = (const float*)d_in[1];
    const float* supports = (const float*)d_in[2];
    const float* W_ru     = (const float*)d_in[3];
    const float* b_ru     = (const float*)d_in[4];
    const float* W_c      = (const float*)d_in[5];
    const float* b_c      = (const float*)d_in[6];
    float* out = (float*)d_out;

    float *pPRE;
    __nv_bfloat16 *pSb, *pXb, *pT1ab, *pT1cb, *pT2ab, *pT2cb, *pWrub, *pWcb;
    cudaGetSymbolAddress((void**)&pPRE,  g_PRE);
    cudaGetSymbolAddress((void**)&pSb,   g_Sb);
    cudaGetSymbolAddress((void**)&pXb,   g_Xb);
    cudaGetSymbolAddress((void**)&pT1ab, g_T1ab);
    cudaGetSymbolAddress((void**)&pT1cb, g_T1cb);
    cudaGetSymbolAddress((void**)&pT2ab, g_T2ab);
    cudaGetSymbolAddress((void**)&pT2cb, g_T2cb);
    cudaGetSymbolAddress((void**)&pWrub, g_Wrub);
    cudaGetSymbolAddress((void**)&pWcb,  g_Wcb);

    float* pPREC = pPRE + (size_t)NN * NB * DCAT;

    cudaFuncSetAttribute(hgemm_kernel,
                         cudaFuncAttributeMaxDynamicSharedMemorySize, HG_SMEM);

    const __nv_bfloat16* S0b = pSb;
    const __nv_bfloat16* S1b = pSb + (size_t)NN * NN;

    const dim3 blk(256);
    const dim3 gFull2(BD / 128, NN / 128, 2);        // 2048 CTAs
    const dim3 gHalf2(HALF_W / 128, NN / 128, 2);    // 1024 CTAs
    const dim3 gProj(1, (NN * NB) / 128);            // (1, 1024)

    const size_t total = (size_t)NB * NN * DHH;
    const int dup = ((size_t)out_size >= 2 * total) ? 1 : 0;

    // ---- fused prep (S cast + build_x + W casts) ----
    prep_kernel<<<PREP_TOTAL, blk>>>(inputs, states, supports, W_ru, W_c,
                                     pXb, pSb, pWrub, pWcb);

    // ---------- phase 1 hops (full width), both supports batched ----------
    hgemm_kernel<<<gFull2, blk, HG_SMEM>>>(S0b, S1b, NN, pXb, pXb, BD,
                                           pT1ab, pT1cb, BD,
                                           (const __nv_bfloat16*)0, (const __nv_bfloat16*)0, 0,
                                           1.f, 0.f, NN);
    hgemm_kernel<<<gFull2, blk, HG_SMEM>>>(S0b, S1b, NN, pT1ab, pT1cb, BD,
                                           pT2ab, pT2cb, BD,
                                           pXb, pXb, BD,
                                           2.f, -1.f, NN);

    // ---------- fused ru projection (K=640, bf16) ----------
    bf16_proj5_kernel<<<gProj, blk>>>(pXb, pT1ab, pT2ab, pT1cb, pT2cb,
                                      pWrub, 2 * DHH, pPRE, b_ru);

    // ---------- gates (r only; u consumed later straight from PRE) ----------
    gate_kernel<<<(NN * NB * 32 + 255) / 256, blk>>>(states, pPRE, pXb);

    // ---------- phase 2 hops (st halves only, width 1024), batched ----------
    hgemm_kernel<<<gHalf2, blk, HG_SMEM>>>(S0b, S1b, NN,
                                           pXb + HALF_W, pXb + HALF_W, BD,
                                           pT1ab + HALF_W, pT1cb + HALF_W, BD,
                                           (const __nv_bfloat16*)0, (const __nv_bfloat16*)0, 0,
                                           1.f, 0.f, NN);
    hgemm_kernel<<<gHalf2, blk, HG_SMEM>>>(S0b, S1b, NN,
                                           pT1ab + HALF_W, pT1cb + HALF_W, BD,
                                           pT2ab + HALF_W, pT2cb + HALF_W, BD,
                                           pXb + HALF_W, pXb + HALF_W, BD,
                                           2.f, -1.f, NN);

    // ---------- fused c projection (K=640, Nc=64, bf16) -> disjoint PREC ----------
    bf16_proj5_kernel<<<gProj, blk>>>(pXb, pT1ab, pT2ab, pT1cb, pT2cb,
                                      pWcb, DHH, pPREC, b_c);

    // ---------- final state (u recomputed from ru-PRE) ----------
    final_kernel<<<(NN * NB * 32 + 255) / 256, blk>>>(states, pPRE, pPREC, out, dup);
}